// round 6
// baseline (speedup 1.0000x reference)
#include <cuda_runtime.h>
#include <math.h>

// Problem constants (fixed by setup_inputs)
#define BB 8
#define NN 1024
#define NTOK (BB*NN)   // 8192
#define HH 8
#define SCALE 0.2236067977499790f  // 1/sqrt(20)

// Blade tables (index space of _BLADES):
// idx: 0:(),1:(0),2:(1),3:(2),4:(3),5:(01),6:(02),7:(03),8:(12),9:(13),10:(23),
//      11:(012),12:(013),13:(023),14:(123),15:(0123)
__constant__ int   c_GRADE[16] = {0,1,1,1,1,2,2,2,2,2,2,3,3,3,3,4};
__constant__ int   c_HAS0[16]  = {0,1,0,0,0,1,1,1,0,0,0,1,1,1,0,1};
__constant__ int   c_PART[16]  = {1,0,5,6,7,2,3,4,11,12,13,8,9,10,15,14}; // idx of blade^e0
__constant__ float c_INNERF[16]= {1,0,1,1,1,0,0,0,1,1,1,0,0,0,1,0};
__constant__ int   c_MASK[16]  = {0,1,2,4,8,3,5,9,6,10,12,7,11,13,14,15};
__constant__ int   c_M2I[16]   = {0,1,2,5,3,6,8,11,4,7,9,12,10,13,14,15};

// Scratch (device globals; no allocation allowed)
__device__ float g_S_mv[NTOK*256];
__device__ float g_S_s [NTOK*32];
__device__ float g_N_mv[NTOK*256];
__device__ float g_N_s [NTOK*32];
__device__ float g_Q_mv[NTOK*768];   // qkv mv (48 ch) / mlp hidden mv (32 ch)
__device__ float g_Q_s [NTOK*96];    // qkv s (96) / mlp hidden s (64)
__device__ float g_A_mv[NTOK*256];   // attn out mv / geo product
__device__ float g_A_s [NTOK*32];    // attn out s / gated scalars

__device__ __forceinline__ float gelu_tanh(float x) {
    float x3 = x*x*x;
    return 0.5f*x*(1.f + tanhf(0.7978845608028654f*(x + 0.044715f*x3)));
}

// ---------------------------------------------------------------------------
// Init: build mv0 from coords, apply input equi-linear, s = bias
// (mv0 blade 0 is zero, so s = win_bs only)
// ---------------------------------------------------------------------------
__device__ __forceinline__ float mv0_val(int a, float x, float y, float z) {
    if (a == 14) return 1.f;
    if (a == 13) return -x;
    if (a == 12) return y;
    if (a == 11) return -z;
    return 0.f;
}

__global__ void k_init(const float* __restrict__ inputs,
                       const float* __restrict__ win_mv,  // (16,1,9)
                       const float* __restrict__ win_bs,  // (32,)
                       float* __restrict__ Smv, float* __restrict__ Ss) {
    int wid = threadIdx.x >> 5, lane = threadIdx.x & 31;
    int tok = blockIdx.x*8 + wid;
    if (tok >= NTOK) return;
    float x = inputs[tok*3+0], y = inputs[tok*3+1], z = inputs[tok*3+2];
    for (int oi = lane; oi < 256; oi += 32) {
        int o = oi >> 4, a = oi & 15;
        int g = c_GRADE[a];
        float v = __ldg(&win_mv[o*9+g]) * mv0_val(a,x,y,z);
        if (c_HAS0[a]) v += __ldg(&win_mv[o*9+4+g]) * mv0_val(c_PART[a],x,y,z);
        Smv[(size_t)tok*256 + oi] = v;
    }
    Ss[(size_t)tok*32 + lane] = __ldg(&win_bs[lane]);
}

// ---------------------------------------------------------------------------
// Equi layer norm
// ---------------------------------------------------------------------------
__global__ void k_ln(const float* __restrict__ mv, const float* __restrict__ s,
                     float* __restrict__ nmv, float* __restrict__ ns) {
    int wid = threadIdx.x >> 5, lane = threadIdx.x & 31;
    int tok = blockIdx.x*8 + wid;
    if (tok >= NTOK) return;
    const float* m = mv + (size_t)tok*256;
    float acc = 0.f;
    #pragma unroll
    for (int r = 0; r < 8; r++) { float v = m[r*32+lane]; acc += v*v*c_INNERF[lane & 15]; }
    #pragma unroll
    for (int o = 16; o; o >>= 1) acc += __shfl_xor_sync(0xffffffffu, acc, o);
    float r1 = rsqrtf(acc*(1.f/16.f) + 1e-6f);
    const float* sp = s + (size_t)tok*32;
    float sv = sp[lane];
    float a2 = sv*sv;
    #pragma unroll
    for (int o = 16; o; o >>= 1) a2 += __shfl_xor_sync(0xffffffffu, a2, o);
    float r2 = rsqrtf(a2*(1.f/32.f) + 1e-6f);
    #pragma unroll
    for (int r = 0; r < 8; r++) nmv[(size_t)tok*256 + r*32+lane] = m[r*32+lane]*r1;
    ns[(size_t)tok*32+lane] = sv*r2;
}

// ---------------------------------------------------------------------------
// Equi-linear using BASIS sparsity (static smem only, <= 48KB):
// y_mv[o,a] = sum_i wmv[o,i,g(a)]*x[i,a] + (e0 in a) sum_i wmv[o,i,4+g(a)]*x[i,a\{0}]
//             (+ a==0: wsm@s)
// y_s[o]    = wss@s + wms@x[:,0]
// ---------------------------------------------------------------------------
template<int I, int O, int SI, int SO, bool RES>
__global__ __launch_bounds__(256) void k_equi(
        const float* __restrict__ xmv, const float* __restrict__ xs,
        const float* __restrict__ wmv, const float* __restrict__ wsm,
        const float* __restrict__ wms, const float* __restrict__ wss,
        const float* __restrict__ rmv, const float* __restrict__ rs,
        float* __restrict__ ymv, float* __restrict__ ys) {
    constexpr int WF = O*I*9;
    constexpr int XF = I*16 + SI;
    __shared__ float s_wmv[WF];
    __shared__ float s_x[8*XF];
    int tid = threadIdx.x;
    for (int i = tid; i < WF; i += 256) s_wmv[i] = wmv[i];
    int wid = tid >> 5, lane = tid & 31;
    int tok = blockIdx.x*8 + wid;
    float* xw = s_x + wid*XF;
    for (int i = lane; i < I*16; i += 32) xw[i] = xmv[(size_t)tok*I*16 + i];
    for (int i = lane; i < SI;  i += 32) xw[I*16+i] = xs[(size_t)tok*SI + i];
    __syncthreads();
    for (int oi = lane; oi < O*16 + SO; oi += 32) {
        float acc = 0.f;
        if (oi < O*16) {
            int o = oi >> 4, a = oi & 15;
            int g = c_GRADE[a];
            const float* w = s_wmv + o*I*9;
            #pragma unroll
            for (int i = 0; i < I; i++) acc = fmaf(w[i*9+g], xw[i*16+a], acc);
            if (c_HAS0[a]) {
                int p = c_PART[a]; int k2 = 4+g;
                #pragma unroll
                for (int i = 0; i < I; i++) acc = fmaf(w[i*9+k2], xw[i*16+p], acc);
            }
            if (a == 0) {
                const float* w2 = wsm + o*SI;
                #pragma unroll
                for (int j = 0; j < SI; j++) acc = fmaf(__ldg(&w2[j]), xw[I*16+j], acc);
            }
            if (RES) acc += rmv[(size_t)tok*O*16 + oi];
            ymv[(size_t)tok*O*16 + oi] = acc;
        } else {
            int o = oi - O*16;
            const float* w2 = wss + o*SI;
            #pragma unroll
            for (int j = 0; j < SI; j++) acc = fmaf(__ldg(&w2[j]), xw[I*16+j], acc);
            const float* w3 = wms + o*I;
            #pragma unroll
            for (int i = 0; i < I; i++) acc = fmaf(__ldg(&w3[i]), xw[i*16], acc);
            if (RES) acc += rs[(size_t)tok*SO + o];
            ys[(size_t)tok*SO + o] = acc;
        }
    }
}

// ---------------------------------------------------------------------------
// Flash attention (fp32): head dim = 2*16 mv + 4 s = 36, INNER folded into q.
// Block: 64 q-rows x full head; 256 threads.
// ---------------------------------------------------------------------------
#define KD 36
#define KDP 37
__global__ __launch_bounds__(256) void k_attn(
        const float* __restrict__ qkv_mv, const float* __restrict__ qkv_s,
        float* __restrict__ omv, float* __restrict__ os) {
    __shared__ float qs[64*KDP], ks[64*KDP], vs[64*KDP];
    __shared__ float ps[64*64];
    __shared__ float m_s[64], l_s[64], corr_s[64];
    int tid = threadIdx.x;
    int bh = blockIdx.y, b = bh >> 3, h = bh & 7;
    int qtok0 = b*NN + blockIdx.x*64;
    for (int idx = tid; idx < 64*KD; idx += 256) {
        int r = idx / KD, d = idx - r*KD;
        int t = qtok0 + r;
        float v;
        if (d < 32) { int c = d >> 4, i = d & 15;
            v = qkv_mv[(size_t)t*768 + (h*2+c)*16 + i] * c_INNERF[i]; }
        else v = qkv_s[(size_t)t*96 + h*4 + (d-32)];
        qs[r*KDP + d] = v;
    }
    if (tid < 64) { m_s[tid] = -1e30f; l_s[tid] = 0.f; }
    int orow = tid >> 2, ogl = tid & 3;            // o-phase: 1 row x 9 dims
    float o[9];
    #pragma unroll
    for (int i = 0; i < 9; i++) o[i] = 0.f;
    int rq = tid >> 4, kl = tid & 15;              // score-phase: 4 rows x 4 keys
    int ktok0 = b*NN;
    for (int kt = 0; kt < NN/64; kt++) {
        __syncthreads();
        for (int idx = tid; idx < 64*KD; idx += 256) {
            int r = idx / KD, d = idx - r*KD;
            int t = ktok0 + kt*64 + r;
            float kv, vv;
            if (d < 32) { int c = d >> 4, i = d & 15;
                size_t base = (size_t)t*768 + (h*2+c)*16 + i;
                kv = qkv_mv[base + 256]; vv = qkv_mv[base + 512]; }
            else { size_t base = (size_t)t*96 + h*4 + (d-32);
                kv = qkv_s[base + 32]; vv = qkv_s[base + 64]; }
            ks[r*KDP + d] = kv; vs[r*KDP + d] = vv;
        }
        __syncthreads();
        float sc[4][4];
        #pragma unroll
        for (int i = 0; i < 4; i++)
            #pragma unroll
            for (int j = 0; j < 4; j++) sc[i][j] = 0.f;
        for (int d = 0; d < KD; d++) {
            float q4[4], k4[4];
            #pragma unroll
            for (int i = 0; i < 4; i++) q4[i] = qs[(rq*4+i)*KDP + d];
            #pragma unroll
            for (int j = 0; j < 4; j++) k4[j] = ks[(kl*4+j)*KDP + d];
            #pragma unroll
            for (int i = 0; i < 4; i++)
                #pragma unroll
                for (int j = 0; j < 4; j++) sc[i][j] = fmaf(q4[i], k4[j], sc[i][j]);
        }
        #pragma unroll
        for (int i = 0; i < 4; i++) {
            float tm = -1e30f;
            #pragma unroll
            for (int j = 0; j < 4; j++) { sc[i][j] *= SCALE; tm = fmaxf(tm, sc[i][j]); }
            #pragma unroll
            for (int ofs = 1; ofs < 16; ofs <<= 1)
                tm = fmaxf(tm, __shfl_xor_sync(0xffffffffu, tm, ofs));
            int row = rq*4 + i;
            float mo = m_s[row];
            float nm = fmaxf(mo, tm);
            float sum = 0.f;
            #pragma unroll
            for (int j = 0; j < 4; j++) {
                float p = __expf(sc[i][j] - nm);
                sum += p;
                ps[row*64 + kl*4 + j] = p;
            }
            #pragma unroll
            for (int ofs = 1; ofs < 16; ofs <<= 1)
                sum += __shfl_xor_sync(0xffffffffu, sum, ofs);
            if (kl == 0) {
                float corr = __expf(mo - nm);
                corr_s[row] = corr;
                m_s[row] = nm;
                l_s[row] = l_s[row]*corr + sum;
            }
        }
        __syncthreads();
        float corr = corr_s[orow];
        #pragma unroll
        for (int dd = 0; dd < 9; dd++) o[dd] *= corr;
        for (int key = 0; key < 64; key++) {
            float pv = ps[orow*64 + key];
            #pragma unroll
            for (int dd = 0; dd < 9; dd++)
                o[dd] = fmaf(pv, vs[key*KDP + ogl*9 + dd], o[dd]);
        }
    }
    __syncthreads();
    float inv = 1.f / l_s[orow];
    int t = qtok0 + orow;
    #pragma unroll
    for (int dd = 0; dd < 9; dd++) {
        int d = ogl*9 + dd;
        float val = o[dd]*inv;
        if (d < 32) omv[(size_t)t*256 + (h*2 + (d>>4))*16 + (d&15)] = val;
        else        os[(size_t)t*32 + h*4 + (d-32)] = val;
    }
}

// ---------------------------------------------------------------------------
// Geometric product + gelu gates. 16 tokens x 16 channels per block.
// ---------------------------------------------------------------------------
__global__ __launch_bounds__(256) void k_geo(
        const float* __restrict__ hmv, const float* __restrict__ hs,
        float* __restrict__ gp_mv, float* __restrict__ sh) {
    __shared__ signed char s_pi[16][16], s_pj[16][16];
    __shared__ float s_sg[16][16];
    __shared__ int s_cnt[16];
    __shared__ float s_h[16*512];
    int tid = threadIdx.x;
    if (tid == 0) {
        for (int k = 0; k < 16; k++) s_cnt[k] = 0;
        for (int i = 0; i < 16; i++)
            for (int j = 0; j < 16; j++) {
                int mi = c_MASK[i], mj = c_MASK[j];
                if (mi & mj & 1) continue;     // e0*e0 = 0
                int k = c_M2I[mi ^ mj];
                int inv = 0;
                for (int y = 0; y < 4; y++)
                    if ((mj >> y) & 1) inv += __popc(mi >> (y+1));
                int c = s_cnt[k]++;
                s_pi[k][c] = (signed char)i;
                s_pj[k][c] = (signed char)j;
                s_sg[k][c] = (inv & 1) ? -1.f : 1.f;
            }
    }
    int tok0 = blockIdx.x * 16;
    for (int i = tid; i < 16*512; i += 256) s_h[i] = hmv[(size_t)tok0*512 + i];
    __syncthreads();
    int lt = tid >> 4, ch = tid & 15;
    int tok = tok0 + lt;
    const float* a = s_h + lt*512 + ch*16;
    const float* bv = a + 256;
    float g[16];
    #pragma unroll
    for (int k = 0; k < 16; k++) {
        float acc = 0.f;
        int n = s_cnt[k];
        for (int e = 0; e < n; e++)
            acc = fmaf(s_sg[k][e], a[s_pi[k][e]] * bv[s_pj[k][e]], acc);
        g[k] = acc;
    }
    float gate = gelu_tanh(g[0]);
    #pragma unroll
    for (int k = 0; k < 16; k++)
        gp_mv[(size_t)tok*256 + ch*16 + k] = g[k]*gate;
    for (int j = ch; j < 32; j += 16) {
        float x1 = hs[(size_t)tok*64 + j];
        float x2 = hs[(size_t)tok*64 + 32 + j];
        sh[(size_t)tok*32 + j] = x1 * gelu_tanh(x2);
    }
}

// ---------------------------------------------------------------------------
// Final readout: out[b] = mean_n ( sum_i wout_mv[0,i,0]*mv[i,0] + wout_sm@s )
// ---------------------------------------------------------------------------
__global__ void k_final(const float* __restrict__ Smv, const float* __restrict__ Ss,
                        const float* __restrict__ wout_mv, const float* __restrict__ wout_sm,
                        float* __restrict__ out) {
    __shared__ float red[256];
    int b = blockIdx.x;
    float acc = 0.f;
    for (int n = threadIdx.x; n < NN; n += 256) {
        size_t t = (size_t)b*NN + n;
        float v = 0.f;
        #pragma unroll
        for (int i = 0; i < 16; i++) v = fmaf(__ldg(&wout_mv[i*9]), Smv[t*256 + i*16], v);
        #pragma unroll
        for (int j = 0; j < 32; j++) v = fmaf(__ldg(&wout_sm[j]), Ss[t*32 + j], v);
        acc += v;
    }
    red[threadIdx.x] = acc;
    __syncthreads();
    for (int s = 128; s; s >>= 1) {
        if (threadIdx.x < s) red[threadIdx.x] += red[threadIdx.x + s];
        __syncthreads();
    }
    if (threadIdx.x == 0) out[b] = red[0] * (1.f/NN);
}

// ---------------------------------------------------------------------------
// Host
// ---------------------------------------------------------------------------
template<int I, int O, int SI, int SO, bool RES>
static void launch_equi(const float* xmv, const float* xs,
                        const float* wmv, const float* wsm,
                        const float* wms, const float* wss,
                        const float* rmv, const float* rs,
                        float* ymv, float* ys) {
    k_equi<I,O,SI,SO,RES><<<NTOK/8, 256>>>(xmv, xs, wmv, wsm, wms, wss,
                                           rmv, rs, ymv, ys);
}

extern "C" void kernel_launch(void* const* d_in, const int* in_sizes, int n_in,
                              void* d_out, int out_size) {
    const float* inputs    = (const float*)d_in[0];
    const float* win_mv    = (const float*)d_in[1];
    const float* win_bs    = (const float*)d_in[3];
    const float* qkv_wmv   = (const float*)d_in[4];
    const float* qkv_wsm   = (const float*)d_in[5];
    const float* qkv_wms   = (const float*)d_in[6];
    const float* qkv_wss   = (const float*)d_in[7];
    const float* out_wmv   = (const float*)d_in[8];
    const float* out_wsm   = (const float*)d_in[9];
    const float* out_wms   = (const float*)d_in[10];
    const float* out_wss   = (const float*)d_in[11];
    const float* m1_wmv    = (const float*)d_in[12];
    const float* m1_wsm    = (const float*)d_in[13];
    const float* m1_wms    = (const float*)d_in[14];
    const float* m1_wss    = (const float*)d_in[15];
    const float* m2_wmv    = (const float*)d_in[16];
    const float* m2_wsm    = (const float*)d_in[17];
    const float* m2_wms    = (const float*)d_in[18];
    const float* m2_wss    = (const float*)d_in[19];
    const float* wout_mv   = (const float*)d_in[20];
    const float* wout_sm   = (const float*)d_in[21];
    float* out = (float*)d_out;

    int L = in_sizes[4] / (48*16*9);

    float *Smv, *Ss, *Nmv, *Ns, *Qmv, *Qs, *Amv, *As;
    cudaGetSymbolAddress((void**)&Smv, g_S_mv);
    cudaGetSymbolAddress((void**)&Ss,  g_S_s);
    cudaGetSymbolAddress((void**)&Nmv, g_N_mv);
    cudaGetSymbolAddress((void**)&Ns,  g_N_s);
    cudaGetSymbolAddress((void**)&Qmv, g_Q_mv);
    cudaGetSymbolAddress((void**)&Qs,  g_Q_s);
    cudaGetSymbolAddress((void**)&Amv, g_A_mv);
    cudaGetSymbolAddress((void**)&As,  g_A_s);

    k_init<<<NTOK/8, 256>>>(inputs, win_mv, win_bs, Smv, Ss);

    for (int l = 0; l < L; l++) {
        // --- attention block ---
        k_ln<<<NTOK/8, 256>>>(Smv, Ss, Nmv, Ns);
        launch_equi<16,48,32,96,false>(Nmv, Ns,
            qkv_wmv + (size_t)l*48*16*9, qkv_wsm + (size_t)l*48*32,
            qkv_wms + (size_t)l*96*16,   qkv_wss + (size_t)l*96*32,
            nullptr, nullptr, Qmv, Qs);
        k_attn<<<dim3(NN/64, BB*HH), 256>>>(Qmv, Qs, Amv, As);
        launch_equi<16,16,32,32,true>(Amv, As,
            out_wmv + (size_t)l*16*16*9, out_wsm + (size_t)l*16*32,
            out_wms + (size_t)l*32*16,   out_wss + (size_t)l*32*32,
            Smv, Ss, Smv, Ss);
        // --- mlp block ---
        k_ln<<<NTOK/8, 256>>>(Smv, Ss, Nmv, Ns);
        launch_equi<16,32,32,64,false>(Nmv, Ns,
            m1_wmv + (size_t)l*32*16*9, m1_wsm + (size_t)l*32*32,
            m1_wms + (size_t)l*64*16,   m1_wss + (size_t)l*64*32,
            nullptr, nullptr, Qmv, Qs);
        k_geo<<<NTOK/16, 256>>>(Qmv, Qs, Amv, As);
        launch_equi<16,16,32,32,true>(Amv, As,
            m2_wmv + (size_t)l*16*16*9, m2_wsm + (size_t)l*16*32,
            m2_wms + (size_t)l*32*16,   m2_wss + (size_t)l*32*32,
            Smv, Ss, Smv, Ss);
    }

    k_final<<<BB, 256>>>(Smv, Ss, wout_mv, wout_sm, out);
}

// round 8
// speedup vs baseline: 1.6607x; 1.6607x over previous
#include <cuda_runtime.h>
#include <math.h>

// Problem constants (fixed by setup_inputs)
#define BB 8
#define NN 1024
#define NTOK (BB*NN)   // 8192
#define HH 8
#define SCALE 0.2236067977499790f  // 1/sqrt(20)

// ---------------------------------------------------------------------------
// Compile-time blade tables.
// idx: 0:(),1:(0),2:(1),3:(2),4:(3),5:(01),6:(02),7:(03),8:(12),9:(13),10:(23),
//      11:(012),12:(013),13:(023),14:(123),15:(0123)
// ---------------------------------------------------------------------------
constexpr int BL_GRADE[16]= {0,1,1,1,1,2,2,2,2,2,2,3,3,3,3,4};
constexpr int BL_PART[16] = {1,0,5,6,7,2,3,4,11,12,13,8,9,10,15,14}; // blade^e0
constexpr unsigned INNER_M = 0x471Du;   // 1 if e0 not in blade
constexpr unsigned HAS0_M  = 0xB8E2u;   // 1 if e0 in blade

constexpr unsigned long long pack4(const int (&t)[16]) {
    unsigned long long v = 0;
    for (int i = 0; i < 16; i++) v |= (unsigned long long)t[i] << (4*i);
    return v;
}
constexpr unsigned long long GRADE_P = pack4(BL_GRADE);
constexpr unsigned long long PART_P  = pack4(BL_PART);

__host__ __device__ constexpr int gp_sign(int i, int j) {  // sign of blade_i*blade_j, 0 if e0*e0
    const int M[16] = {0,1,2,4,8,3,5,9,6,10,12,7,11,13,14,15};
    int mi = M[i], mj = M[j];
    if (mi & mj & 1) return 0;
    int inv = 0;
    for (int y = 0; y < 4; y++)
        if ((mj >> y) & 1)
            for (int z = y+1; z < 4; z++) inv += (mi >> z) & 1;
    return (inv & 1) ? -1 : 1;
}
__host__ __device__ constexpr int gp_out(int i, int j) {
    const int M[16]   = {0,1,2,4,8,3,5,9,6,10,12,7,11,13,14,15};
    const int M2I[16] = {0,1,2,5,3,6,8,11,4,7,9,12,10,13,14,15};
    return M2I[M[i] ^ M[j]];
}

// Scratch (device globals; no allocation allowed)
__device__ float g_S_mv[NTOK*256];
__device__ float g_S_s [NTOK*32];
__device__ float g_Q_mv[NTOK*768];   // qkv mv (48 ch) / mlp hidden mv (32 ch)
__device__ float g_Q_s [NTOK*96];    // qkv s (96) / mlp hidden s (64)
__device__ float g_A_mv[NTOK*256];   // attn out mv / geo product
__device__ float g_A_s [NTOK*32];    // attn out s / gated scalars

__device__ __forceinline__ float gelu_tanh(float x) {
    float x3 = x*x*x;
    return 0.5f*x*(1.f + tanhf(0.7978845608028654f*(x + 0.044715f*x3)));
}

// ---------------------------------------------------------------------------
// Init: build mv0 from coords, apply input equi-linear, s = bias
// ---------------------------------------------------------------------------
__device__ __forceinline__ float mv0_val(int a, float x, float y, float z) {
    if (a == 14) return 1.f;
    if (a == 13) return -x;
    if (a == 12) return y;
    if (a == 11) return -z;
    return 0.f;
}

__global__ void k_init(const float* __restrict__ inputs,
                       const float* __restrict__ win_mv,  // (16,1,9)
                       const float* __restrict__ win_bs,  // (32,)
                       float* __restrict__ Smv, float* __restrict__ Ss) {
    int wid = threadIdx.x >> 5, lane = threadIdx.x & 31;
    int tok = blockIdx.x*8 + wid;
    if (tok >= NTOK) return;
    float x = inputs[tok*3+0], y = inputs[tok*3+1], z = inputs[tok*3+2];
    int a = lane & 15;
    int g = (int)((GRADE_P >> (4*a)) & 15);
    int p = (int)((PART_P  >> (4*a)) & 15);
    int h0 = (HAS0_M >> a) & 1;
    float va = mv0_val(a,x,y,z), vp = mv0_val(p,x,y,z);
    for (int oi = lane; oi < 256; oi += 32) {
        int o = oi >> 4;
        float v = __ldg(&win_mv[o*9+g]) * va;
        if (h0) v += __ldg(&win_mv[o*9+4+g]) * vp;
        Smv[(size_t)tok*256 + oi] = v;
    }
    Ss[(size_t)tok*32 + lane] = __ldg(&win_bs[lane]);
}

// ---------------------------------------------------------------------------
// Equi-linear with fused optional LayerNorm, BASIS sparsity, x in registers.
// y_mv[o,a] = sum_i wmv[o,i,g(a)]*x[i,a] + (e0 in a) sum_i wmv[o,i,4+g(a)]*x[i,a\0]
//             (+ a==0: wsm@s)
// y_s[o]    = wss@s + wms@x[:,0]
// One warp = one token. I = 16, SI = 32 always.
// ---------------------------------------------------------------------------
template<int I, int O, int SI, int SO, bool RES, bool LN>
__global__ __launch_bounds__(256) void k_equi(
        const float* __restrict__ xmv, const float* __restrict__ xs,
        const float* __restrict__ wmv, const float* __restrict__ wsm,
        const float* __restrict__ wms, const float* __restrict__ wss,
        const float* __restrict__ rmv, const float* __restrict__ rs,
        float* __restrict__ ymv, float* __restrict__ ys) {
    constexpr int WF = O*I*9;
    __shared__ float s_wk[WF];          // relaid out: [k][o][i]
    __shared__ float s_ts[8][SI + I];   // raw s (SI) then x[:,0] (I)
    __shared__ float s_ex[8][O];        // blade-0 scalar->mv contributions
    int tid = threadIdx.x;
    for (int idx = tid; idx < WF; idx += 256) {
        int o = idx / (I*9); int r = idx - o*(I*9); int i = r / 9; int k = r - i*9;
        s_wk[(k*O + o)*I + i] = wmv[idx];
    }
    int wid = tid >> 5, lane = tid & 31;
    int tok = blockIdx.x*8 + wid;
    int a = lane & 15;
    int g  = (int)((GRADE_P >> (4*a)) & 15);
    int pp = (int)((PART_P  >> (4*a)) & 15);
    int h0 = (HAS0_M >> a) & 1;
    const float* xm = xmv + (size_t)tok*(I*16);
    float xa[I], xp[I];
    #pragma unroll
    for (int i = 0; i < I; i++) { xa[i] = xm[i*16 + a]; xp[i] = xm[i*16 + pp]; }
    float sv = xs[(size_t)tok*SI + lane];
    s_ts[wid][lane] = sv;
    if (lane < I) s_ts[wid][SI + lane] = xm[lane*16];
    float r1 = 1.f, r2 = 1.f;
    if (LN) {
        float innf = ((INNER_M >> a) & 1) ? 1.f : 0.f;
        float acc = 0.f;
        #pragma unroll
        for (int i = 0; i < I; i++) acc += xa[i]*xa[i];
        acc *= innf;
        #pragma unroll
        for (int ofs = 1; ofs < 16; ofs <<= 1) acc += __shfl_xor_sync(0xffffffffu, acc, ofs);
        r1 = rsqrtf(acc*(1.f/(float)I) + 1e-6f);
        float a2 = sv*sv;
        #pragma unroll
        for (int ofs = 1; ofs < 32; ofs <<= 1) a2 += __shfl_xor_sync(0xffffffffu, a2, ofs);
        r2 = rsqrtf(a2*(1.f/(float)SI) + 1e-6f);
        #pragma unroll
        for (int i = 0; i < I; i++) { xa[i] *= r1; xp[i] *= r1; }
    }
    __syncthreads();
    // blade-0 scalar->mv contributions (wsm @ s), distributed over lanes
    for (int o = lane; o < O; o += 32) {
        const float4* w4 = reinterpret_cast<const float4*>(wsm + o*SI);
        float acc = 0.f;
        #pragma unroll
        for (int j4 = 0; j4 < SI/4; j4++) {
            float4 w = __ldg(&w4[j4]);
            acc = fmaf(w.x, s_ts[wid][j4*4+0], acc);
            acc = fmaf(w.y, s_ts[wid][j4*4+1], acc);
            acc = fmaf(w.z, s_ts[wid][j4*4+2], acc);
            acc = fmaf(w.w, s_ts[wid][j4*4+3], acc);
        }
        s_ex[wid][o] = acc * r2;
    }
    __syncwarp();
    // main mv outputs
    for (int oi = lane; oi < O*16; oi += 32) {
        int o = oi >> 4;
        const float4* w1 = reinterpret_cast<const float4*>(&s_wk[(g*O + o)*I]);
        float acc = 0.f;
        #pragma unroll
        for (int i4 = 0; i4 < I/4; i4++) {
            float4 w = w1[i4];
            acc = fmaf(w.x, xa[i4*4+0], acc);
            acc = fmaf(w.y, xa[i4*4+1], acc);
            acc = fmaf(w.z, xa[i4*4+2], acc);
            acc = fmaf(w.w, xa[i4*4+3], acc);
        }
        if (h0) {
            const float4* w2 = reinterpret_cast<const float4*>(&s_wk[((4+g)*O + o)*I]);
            #pragma unroll
            for (int i4 = 0; i4 < I/4; i4++) {
                float4 w = w2[i4];
                acc = fmaf(w.x, xp[i4*4+0], acc);
                acc = fmaf(w.y, xp[i4*4+1], acc);
                acc = fmaf(w.z, xp[i4*4+2], acc);
                acc = fmaf(w.w, xp[i4*4+3], acc);
            }
        }
        if (a == 0) acc += s_ex[wid][o];
        if (RES) acc += rmv[(size_t)tok*O*16 + oi];
        ymv[(size_t)tok*O*16 + oi] = acc;
    }
    // scalar outputs
    for (int so = lane; so < SO; so += 32) {
        const float4* ws4 = reinterpret_cast<const float4*>(wss + so*SI);
        float accs = 0.f;
        #pragma unroll
        for (int j4 = 0; j4 < SI/4; j4++) {
            float4 w = __ldg(&ws4[j4]);
            accs = fmaf(w.x, s_ts[wid][j4*4+0], accs);
            accs = fmaf(w.y, s_ts[wid][j4*4+1], accs);
            accs = fmaf(w.z, s_ts[wid][j4*4+2], accs);
            accs = fmaf(w.w, s_ts[wid][j4*4+3], accs);
        }
        const float4* wm4 = reinterpret_cast<const float4*>(wms + so*I);
        float accm = 0.f;
        #pragma unroll
        for (int i4 = 0; i4 < I/4; i4++) {
            float4 w = __ldg(&wm4[i4]);
            accm = fmaf(w.x, s_ts[wid][SI + i4*4+0], accm);
            accm = fmaf(w.y, s_ts[wid][SI + i4*4+1], accm);
            accm = fmaf(w.z, s_ts[wid][SI + i4*4+2], accm);
            accm = fmaf(w.w, s_ts[wid][SI + i4*4+3], accm);
        }
        float acc = accs*r2 + accm*r1;
        if (RES) acc += rs[(size_t)tok*SO + so];
        ys[(size_t)tok*SO + so] = acc;
    }
}

// ---------------------------------------------------------------------------
// Flash attention (fp32): head dim = 2*16 mv + 4 s = 36, INNER folded into q.
// Score phase: 4x4 register tiles.  O-phase: 4 rows x 9 dims x 4-way key split.
// ---------------------------------------------------------------------------
#define KD 36
#define KDP 37
#define PSP 65
__global__ __launch_bounds__(256) void k_attn(
        const float* __restrict__ qkv_mv, const float* __restrict__ qkv_s,
        float* __restrict__ omv, float* __restrict__ os) {
    __shared__ float qs[64*KDP], ks[64*KDP], vs[64*KDP];
    __shared__ float ps[64*PSP];
    __shared__ float m_s[64], l_s[64], corr_s[64];
    int tid = threadIdx.x;
    int bh = blockIdx.y, b = bh >> 3, h = bh & 7;
    int qtok0 = b*NN + blockIdx.x*64;
    for (int idx = tid; idx < 64*KD; idx += 256) {
        int r = idx / KD, d = idx - r*KD;
        int t = qtok0 + r;
        float v;
        if (d < 32) { int c = d >> 4, i = d & 15;
            float innf = ((INNER_M >> i) & 1) ? 1.f : 0.f;
            v = qkv_mv[(size_t)t*768 + (h*2+c)*16 + i] * innf; }
        else v = qkv_s[(size_t)t*96 + h*4 + (d-32)];
        qs[r*KDP + d] = v;
    }
    if (tid < 64) { m_s[tid] = -1e30f; l_s[tid] = 0.f; }
    // o-phase mapping: rq (0..15) rows 4rq..4rq+3; ogl (0..3) 9 dims; ks (0..3) key split
    int rq  = tid >> 4;
    int ogl = (tid >> 2) & 3;
    int kspl= tid & 3;
    float o4[4][9];
    #pragma unroll
    for (int r = 0; r < 4; r++)
        #pragma unroll
        for (int d = 0; d < 9; d++) o4[r][d] = 0.f;
    int kl = tid & 15;   // score phase: rq rows x kl key-quads
    int ktok0 = b*NN;
    for (int kt = 0; kt < NN/64; kt++) {
        __syncthreads();
        for (int idx = tid; idx < 64*KD; idx += 256) {
            int r = idx / KD, d = idx - r*KD;
            int t = ktok0 + kt*64 + r;
            float kv, vv;
            if (d < 32) { int c = d >> 4, i = d & 15;
                size_t base = (size_t)t*768 + (h*2+c)*16 + i;
                kv = qkv_mv[base + 256]; vv = qkv_mv[base + 512]; }
            else { size_t base = (size_t)t*96 + h*4 + (d-32);
                kv = qkv_s[base + 32]; vv = qkv_s[base + 64]; }
            ks[r*KDP + d] = kv; vs[r*KDP + d] = vv;
        }
        __syncthreads();
        // ---- score phase ----
        float sc[4][4];
        #pragma unroll
        for (int i = 0; i < 4; i++)
            #pragma unroll
            for (int j = 0; j < 4; j++) sc[i][j] = 0.f;
        for (int d = 0; d < KD; d++) {
            float q4[4], k4[4];
            #pragma unroll
            for (int i = 0; i < 4; i++) q4[i] = qs[(rq*4+i)*KDP + d];
            #pragma unroll
            for (int j = 0; j < 4; j++) k4[j] = ks[(kl*4+j)*KDP + d];
            #pragma unroll
            for (int i = 0; i < 4; i++)
                #pragma unroll
                for (int j = 0; j < 4; j++) sc[i][j] = fmaf(q4[i], k4[j], sc[i][j]);
        }
        #pragma unroll
        for (int i = 0; i < 4; i++) {
            float tm = -1e30f;
            #pragma unroll
            for (int j = 0; j < 4; j++) { sc[i][j] *= SCALE; tm = fmaxf(tm, sc[i][j]); }
            #pragma unroll
            for (int ofs = 1; ofs < 16; ofs <<= 1)
                tm = fmaxf(tm, __shfl_xor_sync(0xffffffffu, tm, ofs));
            int row = rq*4 + i;
            float mo = m_s[row];
            float nm = fmaxf(mo, tm);
            float sum = 0.f;
            #pragma unroll
            for (int j = 0; j < 4; j++) {
                float pv = __expf(sc[i][j] - nm);
                sum += pv;
                ps[row*PSP + kl*4 + j] = pv;
            }
            #pragma unroll
            for (int ofs = 1; ofs < 16; ofs <<= 1)
                sum += __shfl_xor_sync(0xffffffffu, sum, ofs);
            if (kl == 0) {
                float corr = __expf(mo - nm);
                corr_s[row] = corr;
                m_s[row] = nm;
                l_s[row] = l_s[row]*corr + sum;
            }
        }
        __syncthreads();
        // ---- o accumulation phase ----
        float c4[4];
        #pragma unroll
        for (int r = 0; r < 4; r++) c4[r] = corr_s[rq*4 + r];
        #pragma unroll
        for (int r = 0; r < 4; r++)
            #pragma unroll
            for (int d = 0; d < 9; d++) o4[r][d] *= c4[r];
        int key0 = kspl*16;
        for (int kk = 0; kk < 16; kk++) {
            int key = key0 + kk;
            float p0 = ps[(rq*4+0)*PSP + key];
            float p1 = ps[(rq*4+1)*PSP + key];
            float p2 = ps[(rq*4+2)*PSP + key];
            float p3 = ps[(rq*4+3)*PSP + key];
            const float* vrow = &vs[key*KDP + ogl*9];
            #pragma unroll
            for (int d = 0; d < 9; d++) {
                float v = vrow[d];
                o4[0][d] = fmaf(p0, v, o4[0][d]);
                o4[1][d] = fmaf(p1, v, o4[1][d]);
                o4[2][d] = fmaf(p2, v, o4[2][d]);
                o4[3][d] = fmaf(p3, v, o4[3][d]);
            }
        }
    }
    // reduce key splits (lanes xor 1,2 within groups of 4)
    #pragma unroll
    for (int r = 0; r < 4; r++)
        #pragma unroll
        for (int d = 0; d < 9; d++) {
            float v = o4[r][d];
            v += __shfl_xor_sync(0xffffffffu, v, 1);
            v += __shfl_xor_sync(0xffffffffu, v, 2);
            o4[r][d] = v;
        }
    if (kspl == 0) {
        #pragma unroll
        for (int r = 0; r < 4; r++) {
            int row = rq*4 + r;
            float inv = 1.f / l_s[row];
            int t = qtok0 + row;
            #pragma unroll
            for (int dd = 0; dd < 9; dd++) {
                int d = ogl*9 + dd;
                float val = o4[r][dd]*inv;
                if (d < 32) omv[(size_t)t*256 + (h*2 + (d>>4))*16 + (d&15)] = val;
                else        os[(size_t)t*32 + h*4 + (d-32)] = val;
            }
        }
    }
}

// ---------------------------------------------------------------------------
// Geometric product + gelu gates. Fully unrolled compile-time product table.
// One thread per (token, channel); no shared memory.
// ---------------------------------------------------------------------------
__global__ __launch_bounds__(256) void k_geo(
        const float* __restrict__ hmv, const float* __restrict__ hs,
        float* __restrict__ gp_mv, float* __restrict__ sh) {
    int gid = blockIdx.x*256 + threadIdx.x;
    int tok = gid >> 4, ch = gid & 15;
    const float4* ap = reinterpret_cast<const float4*>(hmv + (size_t)tok*512 + ch*16);
    const float4* bp = reinterpret_cast<const float4*>(hmv + (size_t)tok*512 + 256 + ch*16);
    float av[16], bv[16];
    #pragma unroll
    for (int q = 0; q < 4; q++) {
        float4 va = ap[q], vb = bp[q];
        av[4*q+0]=va.x; av[4*q+1]=va.y; av[4*q+2]=va.z; av[4*q+3]=va.w;
        bv[4*q+0]=vb.x; bv[4*q+1]=vb.y; bv[4*q+2]=vb.z; bv[4*q+3]=vb.w;
    }
    float g[16];
    #pragma unroll
    for (int k = 0; k < 16; k++) g[k] = 0.f;
    #pragma unroll
    for (int i = 0; i < 16; i++) {
        #pragma unroll
        for (int j = 0; j < 16; j++) {
            const int sg = gp_sign(i, j);
            if (sg != 0) {
                const int k = gp_out(i, j);
                g[k] = fmaf((sg > 0 ? av[i] : -av[i]), bv[j], g[k]);
            }
        }
    }
    float gate = gelu_tanh(g[0]);
    float4* op = reinterpret_cast<float4*>(gp_mv + (size_t)tok*256 + ch*16);
    #pragma unroll
    for (int q = 0; q < 4; q++) {
        float4 v;
        v.x = g[4*q+0]*gate; v.y = g[4*q+1]*gate;
        v.z = g[4*q+2]*gate; v.w = g[4*q+3]*gate;
        op[q] = v;
    }
    // scalar gates: 32 outs per token, 16 threads -> 2 each
    #pragma unroll
    for (int r = 0; r < 2; r++) {
        int j = ch + r*16;
        float x1 = hs[(size_t)tok*64 + j];
        float x2 = hs[(size_t)tok*64 + 32 + j];
        sh[(size_t)tok*32 + j] = x1 * gelu_tanh(x2);
    }
}

// ---------------------------------------------------------------------------
// Final readout: out[b] = mean_n ( sum_i wout_mv[0,i,0]*mv[i,0] + wout_sm@s )
// ---------------------------------------------------------------------------
__global__ void k_final(const float* __restrict__ Smv, const float* __restrict__ Ss,
                        const float* __restrict__ wout_mv, const float* __restrict__ wout_sm,
                        float* __restrict__ out) {
    __shared__ float red[256];
    int b = blockIdx.x;
    float acc = 0.f;
    for (int n = threadIdx.x; n < NN; n += 256) {
        size_t t = (size_t)b*NN + n;
        float v = 0.f;
        #pragma unroll
        for (int i = 0; i < 16; i++) v = fmaf(__ldg(&wout_mv[i*9]), Smv[t*256 + i*16], v);
        #pragma unroll
        for (int j = 0; j < 32; j++) v = fmaf(__ldg(&wout_sm[j]), Ss[t*32 + j], v);
        acc += v;
    }
    red[threadIdx.x] = acc;
    __syncthreads();
    for (int s = 128; s; s >>= 1) {
        if (threadIdx.x < s) red[threadIdx.x] += red[threadIdx.x + s];
        __syncthreads();
    }
    if (threadIdx.x == 0) out[b] = red[0] * (1.f/NN);
}

// ---------------------------------------------------------------------------
// Host
// ---------------------------------------------------------------------------
template<int I, int O, int SI, int SO, bool RES, bool LN>
static void launch_equi(const float* xmv, const float* xs,
                        const float* wmv, const float* wsm,
                        const float* wms, const float* wss,
                        const float* rmv, const float* rs,
                        float* ymv, float* ys) {
    k_equi<I,O,SI,SO,RES,LN><<<NTOK/8, 256>>>(xmv, xs, wmv, wsm, wms, wss,
                                              rmv, rs, ymv, ys);
}

extern "C" void kernel_launch(void* const* d_in, const int* in_sizes, int n_in,
                              void* d_out, int out_size) {
    const float* inputs    = (const float*)d_in[0];
    const float* win_mv    = (const float*)d_in[1];
    const float* win_bs    = (const float*)d_in[3];
    const float* qkv_wmv   = (const float*)d_in[4];
    const float* qkv_wsm   = (const float*)d_in[5];
    const float* qkv_wms   = (const float*)d_in[6];
    const float* qkv_wss   = (const float*)d_in[7];
    const float* out_wmv   = (const float*)d_in[8];
    const float* out_wsm   = (const float*)d_in[9];
    const float* out_wms   = (const float*)d_in[10];
    const float* out_wss   = (const float*)d_in[11];
    const float* m1_wmv    = (const float*)d_in[12];
    const float* m1_wsm    = (const float*)d_in[13];
    const float* m1_wms    = (const float*)d_in[14];
    const float* m1_wss    = (const float*)d_in[15];
    const float* m2_wmv    = (const float*)d_in[16];
    const float* m2_wsm    = (const float*)d_in[17];
    const float* m2_wms    = (const float*)d_in[18];
    const float* m2_wss    = (const float*)d_in[19];
    const float* wout_mv   = (const float*)d_in[20];
    const float* wout_sm   = (const float*)d_in[21];
    float* out = (float*)d_out;

    int L = in_sizes[4] / (48*16*9);

    float *Smv, *Ss, *Qmv, *Qs, *Amv, *As;
    cudaGetSymbolAddress((void**)&Smv, g_S_mv);
    cudaGetSymbolAddress((void**)&Ss,  g_S_s);
    cudaGetSymbolAddress((void**)&Qmv, g_Q_mv);
    cudaGetSymbolAddress((void**)&Qs,  g_Q_s);
    cudaGetSymbolAddress((void**)&Amv, g_A_mv);
    cudaGetSymbolAddress((void**)&As,  g_A_s);

    k_init<<<NTOK/8, 256>>>(inputs, win_mv, win_bs, Smv, Ss);

    for (int l = 0; l < L; l++) {
        // --- attention block (LN fused into qkv equi) ---
        launch_equi<16,48,32,96,false,true>(Smv, Ss,
            qkv_wmv + (size_t)l*48*16*9, qkv_wsm + (size_t)l*48*32,
            qkv_wms + (size_t)l*96*16,   qkv_wss + (size_t)l*96*32,
            nullptr, nullptr, Qmv, Qs);
        k_attn<<<dim3(NN/64, BB*HH), 256>>>(Qmv, Qs, Amv, As);
        launch_equi<16,16,32,32,true,false>(Amv, As,
            out_wmv + (size_t)l*16*16*9, out_wsm + (size_t)l*16*32,
            out_wms + (size_t)l*32*16,   out_wss + (size_t)l*32*32,
            Smv, Ss, Smv, Ss);
        // --- mlp block (LN fused into mlp1 equi) ---
        launch_equi<16,32,32,64,false,true>(Smv, Ss,
            m1_wmv + (size_t)l*32*16*9, m1_wsm + (size_t)l*32*32,
            m1_wms + (size_t)l*64*16,   m1_wss + (size_t)l*64*32,
            nullptr, nullptr, Qmv, Qs);
        k_geo<<<NTOK*16/256, 256>>>(Qmv, Qs, Amv, As);
        launch_equi<16,16,32,32,true,false>(Amv, As,
            m2_wmv + (size_t)l*16*16*9, m2_wsm + (size_t)l*16*32,
            m2_wms + (size_t)l*32*16,   m2_wss + (size_t)l*32*32,
            Smv, Ss, Smv, Ss);
    }

    k_final<<<BB, 256>>>(Smv, Ss, wout_mv, wout_sm, out);
}